// round 4
// baseline (speedup 1.0000x reference)
#include <cuda_runtime.h>
#include <cstdint>

#define BB 4
#define SS 2048
#define HH 2048
#define NHH 16
#define HDD 128
#define MROWS (BB*SS)      /* 8192 */
#define QKVN (3*HH)        /* 6144 */

// ---------------- scratch (static device allocations are allowed) ----------
__device__ float g_xn [(size_t)MROWS * HH];
__device__ float g_qkv[(size_t)MROWS * QKVN];
__device__ float g_o  [(size_t)MROWS * HH];

// ---------------- LayerNorm ------------------------------------------------
__global__ void __launch_bounds__(256) ln_kernel(
    const float* __restrict__ x, const float* __restrict__ w,
    const float* __restrict__ b, float* __restrict__ out)
{
    int row = blockIdx.x;
    const float* xr = x + (size_t)row * HH;
    float v[8];
    float s = 0.f, s2 = 0.f;
    #pragma unroll
    for (int i = 0; i < 8; i++) {
        v[i] = xr[threadIdx.x + i * 256];
        s  += v[i];
        s2 += v[i] * v[i];
    }
    __shared__ float red0[8], red1[8];
    #pragma unroll
    for (int off = 16; off; off >>= 1) {
        s  += __shfl_xor_sync(0xffffffffu, s,  off);
        s2 += __shfl_xor_sync(0xffffffffu, s2, off);
    }
    int warp = threadIdx.x >> 5, lane = threadIdx.x & 31;
    if (lane == 0) { red0[warp] = s; red1[warp] = s2; }
    __syncthreads();
    if (warp == 0) {
        s  = red0[lane & 7];
        s2 = red1[lane & 7];
        #pragma unroll
        for (int off = 4; off; off >>= 1) {
            s  += __shfl_xor_sync(0xffffffffu, s,  off);
            s2 += __shfl_xor_sync(0xffffffffu, s2, off);
        }
        if (lane == 0) { red0[0] = s; red1[0] = s2; }
    }
    __syncthreads();
    float mu  = red0[0] * (1.f / HH);
    float var = red1[0] * (1.f / HH) - mu * mu;
    float rs  = rsqrtf(var + 1e-5f);
    float* orow = out + (size_t)row * HH;
    #pragma unroll
    for (int i = 0; i < 8; i++) {
        int c = threadIdx.x + i * 256;
        orow[c] = (v[i] - mu) * rs * w[c] + b[c];
    }
}

// ---------------- TF32 GEMM (C = A@B [+bias] [+res]) -----------------------
__device__ __forceinline__ unsigned f2tf(float f) {
    unsigned u;
    asm("cvt.rna.tf32.f32 %0, %1;" : "=r"(u) : "f"(f));
    return u;
}

#define ASTR 36
#define BSTR 136
#define ASZ (128 * ASTR)
#define BSZ (32 * BSTR)
#define GEMM_SMEM ((2 * (ASZ + BSZ)) * (int)sizeof(float))

template<bool BIAS, bool RES>
__global__ void __launch_bounds__(256) gemm_tf32(
    const float* __restrict__ A, const float* __restrict__ Bm,
    const float* __restrict__ bias, const float* __restrict__ res,
    float* __restrict__ C, int M, int N, int K)
{
    extern __shared__ float sm[];
    float* AsBase = sm;
    float* BsBase = sm + 2 * ASZ;

    int tid  = threadIdx.x;
    int warp = tid >> 5, lane = tid & 31;
    int g = lane >> 2, t = lane & 3;
    int wm = (warp & 3) * 32;
    int wn = (warp >> 2) * 64;
    int bm = blockIdx.y * 128;
    int bn = blockIdx.x * 128;

    float acc[2][8][4];
    #pragma unroll
    for (int i = 0; i < 2; i++)
        #pragma unroll
        for (int j = 0; j < 8; j++)
            #pragma unroll
            for (int c = 0; c < 4; c++) acc[i][j][c] = 0.f;

    const int KT = K >> 5;
    float4 ra[4], rb[4];

    // ---- prologue: load tile 0
    #pragma unroll
    for (int p = 0; p < 4; p++) {
        int idx = tid + p * 256;
        ra[p] = *(const float4*)(A + (size_t)(bm + (idx >> 3)) * K + (idx & 7) * 4);
    }
    #pragma unroll
    for (int p = 0; p < 4; p++) {
        int idx = tid + p * 256;
        rb[p] = *(const float4*)(Bm + (size_t)(idx >> 5) * N + bn + (idx & 31) * 4);
    }
    {
        float* Ab = AsBase; float* Bb = BsBase;
        #pragma unroll
        for (int p = 0; p < 4; p++) {
            int idx = tid + p * 256;
            float* d = Ab + (idx >> 3) * ASTR + (idx & 7) * 4;
            d[0] = __uint_as_float(f2tf(ra[p].x));
            d[1] = __uint_as_float(f2tf(ra[p].y));
            d[2] = __uint_as_float(f2tf(ra[p].z));
            d[3] = __uint_as_float(f2tf(ra[p].w));
        }
        #pragma unroll
        for (int p = 0; p < 4; p++) {
            int idx = tid + p * 256;
            float* d = Bb + (idx >> 5) * BSTR + (idx & 31) * 4;
            d[0] = __uint_as_float(f2tf(rb[p].x));
            d[1] = __uint_as_float(f2tf(rb[p].y));
            d[2] = __uint_as_float(f2tf(rb[p].z));
            d[3] = __uint_as_float(f2tf(rb[p].w));
        }
    }
    __syncthreads();

    for (int kt = 0; kt < KT; kt++) {
        int buf = kt & 1;
        bool has_next = (kt + 1 < KT);
        if (has_next) {
            int kn = kt + 1;
            #pragma unroll
            for (int p = 0; p < 4; p++) {
                int idx = tid + p * 256;
                ra[p] = *(const float4*)(A + (size_t)(bm + (idx >> 3)) * K + kn * 32 + (idx & 7) * 4);
            }
            #pragma unroll
            for (int p = 0; p < 4; p++) {
                int idx = tid + p * 256;
                rb[p] = *(const float4*)(Bm + (size_t)(kn * 32 + (idx >> 5)) * N + bn + (idx & 31) * 4);
            }
        }
        // ---- compute on buf
        {
            float* Ab = AsBase + buf * ASZ;
            float* Bb = BsBase + buf * BSZ;
            #pragma unroll
            for (int ks = 0; ks < 4; ks++) {
                int k0 = ks * 8;
                unsigned af[2][4];
                unsigned bf[8][2];
                #pragma unroll
                for (int mi = 0; mi < 2; mi++) {
                    int rb_ = wm + mi * 16;
                    af[mi][0] = __float_as_uint(Ab[(rb_ + g)     * ASTR + k0 + t]);
                    af[mi][1] = __float_as_uint(Ab[(rb_ + 8 + g) * ASTR + k0 + t]);
                    af[mi][2] = __float_as_uint(Ab[(rb_ + g)     * ASTR + k0 + t + 4]);
                    af[mi][3] = __float_as_uint(Ab[(rb_ + 8 + g) * ASTR + k0 + t + 4]);
                }
                #pragma unroll
                for (int ni = 0; ni < 8; ni++) {
                    int cn = wn + ni * 8 + g;
                    bf[ni][0] = __float_as_uint(Bb[(k0 + t)     * BSTR + cn]);
                    bf[ni][1] = __float_as_uint(Bb[(k0 + t + 4) * BSTR + cn]);
                }
                #pragma unroll
                for (int mi = 0; mi < 2; mi++)
                    #pragma unroll
                    for (int ni = 0; ni < 8; ni++)
                        asm volatile(
                            "mma.sync.aligned.m16n8k8.row.col.f32.tf32.tf32.f32 "
                            "{%0,%1,%2,%3},{%4,%5,%6,%7},{%8,%9},{%0,%1,%2,%3};"
                            : "+f"(acc[mi][ni][0]), "+f"(acc[mi][ni][1]),
                              "+f"(acc[mi][ni][2]), "+f"(acc[mi][ni][3])
                            : "r"(af[mi][0]), "r"(af[mi][1]), "r"(af[mi][2]), "r"(af[mi][3]),
                              "r"(bf[ni][0]), "r"(bf[ni][1]));
            }
        }
        if (has_next) {
            float* Ab = AsBase + (buf ^ 1) * ASZ;
            float* Bb = BsBase + (buf ^ 1) * BSZ;
            #pragma unroll
            for (int p = 0; p < 4; p++) {
                int idx = tid + p * 256;
                float* d = Ab + (idx >> 3) * ASTR + (idx & 7) * 4;
                d[0] = __uint_as_float(f2tf(ra[p].x));
                d[1] = __uint_as_float(f2tf(ra[p].y));
                d[2] = __uint_as_float(f2tf(ra[p].z));
                d[3] = __uint_as_float(f2tf(ra[p].w));
            }
            #pragma unroll
            for (int p = 0; p < 4; p++) {
                int idx = tid + p * 256;
                float* d = Bb + (idx >> 5) * BSTR + (idx & 31) * 4;
                d[0] = __uint_as_float(f2tf(rb[p].x));
                d[1] = __uint_as_float(f2tf(rb[p].y));
                d[2] = __uint_as_float(f2tf(rb[p].z));
                d[3] = __uint_as_float(f2tf(rb[p].w));
            }
            __syncthreads();
        }
    }

    // ---- epilogue
    #pragma unroll
    for (int mi = 0; mi < 2; mi++) {
        int r0 = bm + wm + mi * 16 + g;
        #pragma unroll
        for (int ni = 0; ni < 8; ni++) {
            int c0 = bn + wn + ni * 8 + 2 * t;
            #pragma unroll
            for (int half = 0; half < 2; half++) {
                int row = r0 + half * 8;
                float2 v;
                v.x = acc[mi][ni][half * 2 + 0];
                v.y = acc[mi][ni][half * 2 + 1];
                if (BIAS) { v.x += bias[c0]; v.y += bias[c0 + 1]; }
                if (RES) {
                    float2 rr = *(const float2*)(res + (size_t)row * N + c0);
                    v.x += rr.x; v.y += rr.y;
                }
                *(float2*)(C + (size_t)row * N + c0) = v;
            }
        }
    }
}

// ---------------- fp32 flash attention -------------------------------------
#define QSTR 129
#define PSTR 68
#define FLASH_SMEM ((3 * 64 * QSTR + 64 * PSTR) * (int)sizeof(float))

__global__ void __launch_bounds__(256) flash_kernel(
    const float* __restrict__ qkv, float* __restrict__ o)
{
    extern __shared__ float sm[];
    float* Qs = sm;
    float* Ks = Qs + 64 * QSTR;
    float* Vs = Ks + 64 * QSTR;
    float* Ps = Vs + 64 * QSTR;

    int tid = threadIdx.x;
    int tx = tid & 15, ty = tid >> 4;
    int qt = (int)(gridDim.x - 1) - (int)blockIdx.x;   // heavy tiles first
    int bh = blockIdx.y;
    int b = bh >> 4, h = bh & 15;
    int q0 = qt * 64;
    size_t rowbase = (size_t)b * SS;
    const float scale = 0.08838834764831845f;  // 1/sqrt(128)

    // load Q (scaled)
    #pragma unroll 8
    for (int p = 0; p < 32; p++) {
        int idx = tid + p * 256;
        int r = idx >> 7, c = idx & 127;
        Qs[r * QSTR + c] = qkv[(rowbase + q0 + r) * QKVN + h * 128 + c] * scale;
    }

    float m_i[4], l_i[4], oacc[4][8];
    #pragma unroll
    for (int i = 0; i < 4; i++) {
        m_i[i] = -1e30f; l_i[i] = 0.f;
        #pragma unroll
        for (int mcol = 0; mcol < 8; mcol++) oacc[i][mcol] = 0.f;
    }

    for (int kt = 0; kt <= qt; kt++) {
        int kb = kt * 64;
        __syncthreads();
        #pragma unroll 8
        for (int p = 0; p < 32; p++) {
            int idx = tid + p * 256;
            int r = idx >> 7, c = idx & 127;
            size_t grow = (rowbase + kb + r) * QKVN + h * 128 + c;
            Ks[r * QSTR + c] = qkv[grow + 2048];
            Vs[r * QSTR + c] = qkv[grow + 4096];
        }
        __syncthreads();

        float s[4][4];
        #pragma unroll
        for (int i = 0; i < 4; i++)
            #pragma unroll
            for (int j = 0; j < 4; j++) s[i][j] = 0.f;

        #pragma unroll 4
        for (int k = 0; k < 128; k++) {
            float qv[4], kv[4];
            #pragma unroll
            for (int i = 0; i < 4; i++) qv[i] = Qs[(4 * ty + i) * QSTR + k];
            #pragma unroll
            for (int j = 0; j < 4; j++) kv[j] = Ks[(tx + 16 * j) * QSTR + k];
            #pragma unroll
            for (int i = 0; i < 4; i++)
                #pragma unroll
                for (int j = 0; j < 4; j++) s[i][j] += qv[i] * kv[j];
        }

        if (kt == qt) {   // diagonal tile: causal mask
            #pragma unroll
            for (int i = 0; i < 4; i++)
                #pragma unroll
                for (int j = 0; j < 4; j++)
                    if (kb + tx + 16 * j > q0 + 4 * ty + i) s[i][j] = -1e30f;
        }

        // online softmax
        #pragma unroll
        for (int i = 0; i < 4; i++) {
            float mx = fmaxf(fmaxf(s[i][0], s[i][1]), fmaxf(s[i][2], s[i][3]));
            #pragma unroll
            for (int off = 8; off; off >>= 1)
                mx = fmaxf(mx, __shfl_xor_sync(0xffffffffu, mx, off));
            float mn = fmaxf(m_i[i], mx);
            float alpha = __expf(m_i[i] - mn);
            float ls = 0.f;
            #pragma unroll
            for (int j = 0; j < 4; j++) {
                float pexp = __expf(s[i][j] - mn);
                s[i][j] = pexp;
                ls += pexp;
            }
            #pragma unroll
            for (int off = 8; off; off >>= 1)
                ls += __shfl_xor_sync(0xffffffffu, ls, off);
            l_i[i] = l_i[i] * alpha + ls;
            m_i[i] = mn;
            #pragma unroll
            for (int mcol = 0; mcol < 8; mcol++) oacc[i][mcol] *= alpha;
        }

        // publish P
        #pragma unroll
        for (int i = 0; i < 4; i++)
            #pragma unroll
            for (int j = 0; j < 4; j++)
                Ps[(4 * ty + i) * PSTR + tx + 16 * j] = s[i][j];
        __syncthreads();

        // O += P @ V
        #pragma unroll 2
        for (int j = 0; j < 64; j++) {
            float pv[4];
            #pragma unroll
            for (int i = 0; i < 4; i++) pv[i] = Ps[(4 * ty + i) * PSTR + j];
            #pragma unroll
            for (int mcol = 0; mcol < 8; mcol++) {
                float vv = Vs[j * QSTR + tx + 16 * mcol];
                #pragma unroll
                for (int i = 0; i < 4; i++) oacc[i][mcol] += pv[i] * vv;
            }
        }
    }

    // epilogue: normalize and write O
    #pragma unroll
    for (int i = 0; i < 4; i++) {
        float inv = 1.0f / l_i[i];
        size_t orow = (rowbase + q0 + 4 * ty + i) * HH + h * 128;
        #pragma unroll
        for (int mcol = 0; mcol < 8; mcol++)
            o[orow + tx + 16 * mcol] = oacc[i][mcol] * inv;
    }
}

// ---------------- launch ----------------------------------------------------
extern "C" void kernel_launch(void* const* d_in, const int* in_sizes, int n_in,
                              void* d_out, int out_size)
{
    const float* x        = (const float*)d_in[0];
    const float* ln_w     = (const float*)d_in[1];
    const float* ln_b     = (const float*)d_in[2];
    const float* c_attn_w = (const float*)d_in[3];
    const float* c_attn_b = (const float*)d_in[4];
    const float* c_proj_w = (const float*)d_in[5];
    const float* c_proj_b = (const float*)d_in[6];
    float* out = (float*)d_out;

    void *p_xn, *p_qkv, *p_o;
    cudaGetSymbolAddress(&p_xn,  g_xn);
    cudaGetSymbolAddress(&p_qkv, g_qkv);
    cudaGetSymbolAddress(&p_o,   g_o);
    float* xn  = (float*)p_xn;
    float* qkv = (float*)p_qkv;
    float* ov  = (float*)p_o;

    cudaFuncSetAttribute(gemm_tf32<true, false>,
                         cudaFuncAttributeMaxDynamicSharedMemorySize, GEMM_SMEM);
    cudaFuncSetAttribute(gemm_tf32<true, true>,
                         cudaFuncAttributeMaxDynamicSharedMemorySize, GEMM_SMEM);
    cudaFuncSetAttribute(flash_kernel,
                         cudaFuncAttributeMaxDynamicSharedMemorySize, FLASH_SMEM);

    // 1. LayerNorm
    ln_kernel<<<MROWS, 256>>>(x, ln_w, ln_b, xn);

    // 2. QKV projection: [8192,2048] @ [2048,6144] + bias
    gemm_tf32<true, false><<<dim3(QKVN / 128, MROWS / 128), 256, GEMM_SMEM>>>(
        xn, c_attn_w, c_attn_b, nullptr, qkv, MROWS, QKVN, HH);

    // 3. causal flash attention
    flash_kernel<<<dim3(SS / 64, BB * NHH), 256, FLASH_SMEM>>>(qkv, ov);

    // 4. output projection + bias + residual
    gemm_tf32<true, true><<<dim3(HH / 128, MROWS / 128), 256, GEMM_SMEM>>>(
        ov, c_proj_w, c_proj_b, x, out, MROWS, HH, HH);
}

// round 5
// speedup vs baseline: 1.8447x; 1.8447x over previous
#include <cuda_runtime.h>
#include <cstdint>

#define BB 4
#define SS 2048
#define HH 2048
#define NHH 16
#define HDD 128
#define MROWS (BB*SS)      /* 8192 */
#define QKVN (3*HH)        /* 6144 */

// ---------------- scratch (static device allocations are allowed) ----------
__device__ float g_xn [(size_t)MROWS * HH];
__device__ float g_qkv[(size_t)MROWS * QKVN];
__device__ float g_o  [(size_t)MROWS * HH];

// ---------------- LayerNorm ------------------------------------------------
__global__ void __launch_bounds__(256) ln_kernel(
    const float* __restrict__ x, const float* __restrict__ w,
    const float* __restrict__ b, float* __restrict__ out)
{
    int row = blockIdx.x;
    const float* xr = x + (size_t)row * HH;
    float v[8];
    float s = 0.f, s2 = 0.f;
    #pragma unroll
    for (int i = 0; i < 8; i++) {
        v[i] = xr[threadIdx.x + i * 256];
        s  += v[i];
        s2 += v[i] * v[i];
    }
    __shared__ float red0[8], red1[8];
    #pragma unroll
    for (int off = 16; off; off >>= 1) {
        s  += __shfl_xor_sync(0xffffffffu, s,  off);
        s2 += __shfl_xor_sync(0xffffffffu, s2, off);
    }
    int warp = threadIdx.x >> 5, lane = threadIdx.x & 31;
    if (lane == 0) { red0[warp] = s; red1[warp] = s2; }
    __syncthreads();
    if (warp == 0) {
        s  = red0[lane & 7];
        s2 = red1[lane & 7];
        #pragma unroll
        for (int off = 4; off; off >>= 1) {
            s  += __shfl_xor_sync(0xffffffffu, s,  off);
            s2 += __shfl_xor_sync(0xffffffffu, s2, off);
        }
        if (lane == 0) { red0[0] = s; red1[0] = s2; }
    }
    __syncthreads();
    float mu  = red0[0] * (1.f / HH);
    float var = red1[0] * (1.f / HH) - mu * mu;
    float rs  = rsqrtf(var + 1e-5f);
    float* orow = out + (size_t)row * HH;
    #pragma unroll
    for (int i = 0; i < 8; i++) {
        int c = threadIdx.x + i * 256;
        orow[c] = (v[i] - mu) * rs * w[c] + b[c];
    }
}

// ---------------- TF32 GEMM (C = A@B [+bias] [+res]) -----------------------
__device__ __forceinline__ unsigned f2tf(float f) {
    unsigned u;
    asm("cvt.rna.tf32.f32 %0, %1;" : "=r"(u) : "f"(f));
    return u;
}

#define ASTR 36
#define BSTR 136
#define ASZ (128 * ASTR)
#define BSZ (32 * BSTR)
#define GEMM_SMEM ((2 * (ASZ + BSZ)) * (int)sizeof(float))

template<bool BIAS, bool RES>
__global__ void __launch_bounds__(256) gemm_tf32(
    const float* __restrict__ A, const float* __restrict__ Bm,
    const float* __restrict__ bias, const float* __restrict__ res,
    float* __restrict__ C, int M, int N, int K)
{
    extern __shared__ float sm[];
    float* AsBase = sm;
    float* BsBase = sm + 2 * ASZ;

    int tid  = threadIdx.x;
    int warp = tid >> 5, lane = tid & 31;
    int g = lane >> 2, t = lane & 3;
    int wm = (warp & 3) * 32;
    int wn = (warp >> 2) * 64;
    int bm = blockIdx.y * 128;
    int bn = blockIdx.x * 128;

    float acc[2][8][4];
    #pragma unroll
    for (int i = 0; i < 2; i++)
        #pragma unroll
        for (int j = 0; j < 8; j++)
            #pragma unroll
            for (int c = 0; c < 4; c++) acc[i][j][c] = 0.f;

    const int KT = K >> 5;
    float4 ra[4], rb[4];

    // ---- prologue: load tile 0
    #pragma unroll
    for (int p = 0; p < 4; p++) {
        int idx = tid + p * 256;
        ra[p] = *(const float4*)(A + (size_t)(bm + (idx >> 3)) * K + (idx & 7) * 4);
    }
    #pragma unroll
    for (int p = 0; p < 4; p++) {
        int idx = tid + p * 256;
        rb[p] = *(const float4*)(Bm + (size_t)(idx >> 5) * N + bn + (idx & 31) * 4);
    }
    {
        float* Ab = AsBase; float* Bb = BsBase;
        #pragma unroll
        for (int p = 0; p < 4; p++) {
            int idx = tid + p * 256;
            float* d = Ab + (idx >> 3) * ASTR + (idx & 7) * 4;
            d[0] = __uint_as_float(f2tf(ra[p].x));
            d[1] = __uint_as_float(f2tf(ra[p].y));
            d[2] = __uint_as_float(f2tf(ra[p].z));
            d[3] = __uint_as_float(f2tf(ra[p].w));
        }
        #pragma unroll
        for (int p = 0; p < 4; p++) {
            int idx = tid + p * 256;
            float* d = Bb + (idx >> 5) * BSTR + (idx & 31) * 4;
            d[0] = __uint_as_float(f2tf(rb[p].x));
            d[1] = __uint_as_float(f2tf(rb[p].y));
            d[2] = __uint_as_float(f2tf(rb[p].z));
            d[3] = __uint_as_float(f2tf(rb[p].w));
        }
    }
    __syncthreads();

    for (int kt = 0; kt < KT; kt++) {
        int buf = kt & 1;
        bool has_next = (kt + 1 < KT);
        if (has_next) {
            int kn = kt + 1;
            #pragma unroll
            for (int p = 0; p < 4; p++) {
                int idx = tid + p * 256;
                ra[p] = *(const float4*)(A + (size_t)(bm + (idx >> 3)) * K + kn * 32 + (idx & 7) * 4);
            }
            #pragma unroll
            for (int p = 0; p < 4; p++) {
                int idx = tid + p * 256;
                rb[p] = *(const float4*)(Bm + (size_t)(kn * 32 + (idx >> 5)) * N + bn + (idx & 31) * 4);
            }
        }
        // ---- compute on buf
        {
            float* Ab = AsBase + buf * ASZ;
            float* Bb = BsBase + buf * BSZ;
            #pragma unroll
            for (int ks = 0; ks < 4; ks++) {
                int k0 = ks * 8;
                unsigned af[2][4];
                unsigned bf[8][2];
                #pragma unroll
                for (int mi = 0; mi < 2; mi++) {
                    int rb_ = wm + mi * 16;
                    af[mi][0] = __float_as_uint(Ab[(rb_ + g)     * ASTR + k0 + t]);
                    af[mi][1] = __float_as_uint(Ab[(rb_ + 8 + g) * ASTR + k0 + t]);
                    af[mi][2] = __float_as_uint(Ab[(rb_ + g)     * ASTR + k0 + t + 4]);
                    af[mi][3] = __float_as_uint(Ab[(rb_ + 8 + g) * ASTR + k0 + t + 4]);
                }
                #pragma unroll
                for (int ni = 0; ni < 8; ni++) {
                    int cn = wn + ni * 8 + g;
                    bf[ni][0] = __float_as_uint(Bb[(k0 + t)     * BSTR + cn]);
                    bf[ni][1] = __float_as_uint(Bb[(k0 + t + 4) * BSTR + cn]);
                }
                #pragma unroll
                for (int mi = 0; mi < 2; mi++)
                    #pragma unroll
                    for (int ni = 0; ni < 8; ni++)
                        asm volatile(
                            "mma.sync.aligned.m16n8k8.row.col.f32.tf32.tf32.f32 "
                            "{%0,%1,%2,%3},{%4,%5,%6,%7},{%8,%9},{%0,%1,%2,%3};"
                            : "+f"(acc[mi][ni][0]), "+f"(acc[mi][ni][1]),
                              "+f"(acc[mi][ni][2]), "+f"(acc[mi][ni][3])
                            : "r"(af[mi][0]), "r"(af[mi][1]), "r"(af[mi][2]), "r"(af[mi][3]),
                              "r"(bf[ni][0]), "r"(bf[ni][1]));
            }
        }
        if (has_next) {
            float* Ab = AsBase + (buf ^ 1) * ASZ;
            float* Bb = BsBase + (buf ^ 1) * BSZ;
            #pragma unroll
            for (int p = 0; p < 4; p++) {
                int idx = tid + p * 256;
                float* d = Ab + (idx >> 3) * ASTR + (idx & 7) * 4;
                d[0] = __uint_as_float(f2tf(ra[p].x));
                d[1] = __uint_as_float(f2tf(ra[p].y));
                d[2] = __uint_as_float(f2tf(ra[p].z));
                d[3] = __uint_as_float(f2tf(ra[p].w));
            }
            #pragma unroll
            for (int p = 0; p < 4; p++) {
                int idx = tid + p * 256;
                float* d = Bb + (idx >> 5) * BSTR + (idx & 31) * 4;
                d[0] = __uint_as_float(f2tf(rb[p].x));
                d[1] = __uint_as_float(f2tf(rb[p].y));
                d[2] = __uint_as_float(f2tf(rb[p].z));
                d[3] = __uint_as_float(f2tf(rb[p].w));
            }
            __syncthreads();
        }
    }

    // ---- epilogue
    #pragma unroll
    for (int mi = 0; mi < 2; mi++) {
        int r0 = bm + wm + mi * 16 + g;
        #pragma unroll
        for (int ni = 0; ni < 8; ni++) {
            int c0 = bn + wn + ni * 8 + 2 * t;
            #pragma unroll
            for (int half = 0; half < 2; half++) {
                int row = r0 + half * 8;
                float2 v;
                v.x = acc[mi][ni][half * 2 + 0];
                v.y = acc[mi][ni][half * 2 + 1];
                if (BIAS) { v.x += bias[c0]; v.y += bias[c0 + 1]; }
                if (RES) {
                    float2 rr = *(const float2*)(res + (size_t)row * N + c0);
                    v.x += rr.x; v.y += rr.y;
                }
                *(float2*)(C + (size_t)row * N + c0) = v;
            }
        }
    }
}

// ---------------- tensor-core (tf32) flash attention ------------------------
// Block: 256 threads (8 warps). Q tile = 128 rows (16 rows/warp).
// K/V tiles = 64 rows, double-buffered via cp.async (one-ahead prefetch).
// Smem stride 136 floats (8 banks/row) -> all fragment LDS conflict-free.
// P (probs) converted C-frag -> A-frag via quad shuffles (no smem for P).

#define BLKQ 128
#define BLKK 64
#define FSTR 136
#define KVSZ (BLKK * FSTR)
#define FLASH_SMEM ((BLKQ * FSTR + 4 * KVSZ) * (int)sizeof(float))  /* 208896 B */

__device__ __forceinline__ uint32_t smem_u32(const void* p) {
    uint32_t a;
    asm("{ .reg .u64 t; cvta.to.shared.u64 t, %1; cvt.u32.u64 %0, t; }"
        : "=r"(a) : "l"(p));
    return a;
}

__global__ void __launch_bounds__(256) flash_tc_kernel(
    const float* __restrict__ qkv, float* __restrict__ o)
{
    extern __shared__ float sm[];
    float* Qs = sm;                         // [128][FSTR]
    float* KV = sm + BLKQ * FSTR;           // 2 x (K[64][FSTR], V[64][FSTR])

    int tid  = threadIdx.x;
    int warp = tid >> 5, lane = tid & 31;
    int g = lane >> 2, t = lane & 3;
    int qt = 15 - (int)blockIdx.x;          // heavy tiles first
    int bh = blockIdx.y;
    int b = bh >> 4, h = bh & 15;
    int q0 = qt * BLKQ;
    size_t rowbase = (size_t)b * SS;
    size_t hoff = (size_t)h * 128;
    const float scale = 0.08838834764831845f;   // 1/sqrt(128)

    // ---- load Q (scaled) into smem
    #pragma unroll
    for (int i = 0; i < 16; i++) {
        int idx = tid + i * 256;            // 4096 float4s
        int r = idx >> 5, c4 = (idx & 31) * 4;
        float4 v = *(const float4*)(qkv + (rowbase + q0 + r) * QKVN + hoff + c4);
        float* d = Qs + r * FSTR + c4;
        d[0] = v.x * scale; d[1] = v.y * scale;
        d[2] = v.z * scale; d[3] = v.w * scale;
    }

    auto issue_tile = [&](int kt) {
        int kb = kt * BLKK;
        float* Kb = KV + (kt & 1) * 2 * KVSZ;
        float* Vb = Kb + KVSZ;
        #pragma unroll
        for (int i = 0; i < 8; i++) {
            int idx = tid + i * 256;        // 2048 float4s per operand
            int r = idx >> 5, c4 = (idx & 31) * 4;
            const float* gk = qkv + (rowbase + kb + r) * QKVN + hoff + 2048 + c4;
            const float* gv = gk + 2048;
            uint32_t sk = smem_u32(Kb + r * FSTR + c4);
            uint32_t sv = smem_u32(Vb + r * FSTR + c4);
            asm volatile("cp.async.cg.shared.global [%0], [%1], 16;" :: "r"(sk), "l"(gk) : "memory");
            asm volatile("cp.async.cg.shared.global [%0], [%1], 16;" :: "r"(sv), "l"(gv) : "memory");
        }
        asm volatile("cp.async.commit_group;" ::: "memory");
    };

    float m0 = -1e30f, m1 = -1e30f, l0 = 0.f, l1 = 0.f;
    float oa[16][4];
    #pragma unroll
    for (int nt = 0; nt < 16; nt++)
        #pragma unroll
        for (int c = 0; c < 4; c++) oa[nt][c] = 0.f;

    const int NKT = (q0 + BLKQ) / BLKK;     // 2*qt + 2
    const int myrow0 = q0 + warp * 16;      // first q row of this warp
    const int arow0 = (warp * 16 + g) * FSTR;
    const int arow1 = arow0 + 8 * FSTR;

    issue_tile(0);

    for (int kt = 0; kt < NKT; kt++) {
        int kb = kt * BLKK;
        asm volatile("cp.async.wait_group 0;" ::: "memory");
        __syncthreads();                     // tile kt visible; prev tile's bufs free
        if (kt + 1 < NKT) issue_tile(kt + 1);

        bool active = (kb <= myrow0 + 15);   // warp-uniform
        float* Kb = KV + (kt & 1) * 2 * KVSZ;
        float* Vb = Kb + KVSZ;

        if (active) {
            // ---- S = Q @ K^T  (128 mmas/warp)
            float s[8][4];
            #pragma unroll
            for (int n = 0; n < 8; n++)
                #pragma unroll
                for (int c = 0; c < 4; c++) s[n][c] = 0.f;

            #pragma unroll
            for (int k = 0; k < 16; k++) {
                int k0 = k * 8;
                uint32_t a0 = __float_as_uint(Qs[arow0 + k0 + t]);
                uint32_t a1 = __float_as_uint(Qs[arow1 + k0 + t]);
                uint32_t a2 = __float_as_uint(Qs[arow0 + k0 + t + 4]);
                uint32_t a3 = __float_as_uint(Qs[arow1 + k0 + t + 4]);
                #pragma unroll
                for (int n = 0; n < 8; n++) {
                    uint32_t b0 = __float_as_uint(Kb[(n * 8 + g) * FSTR + k0 + t]);
                    uint32_t b1 = __float_as_uint(Kb[(n * 8 + g) * FSTR + k0 + t + 4]);
                    asm volatile(
                        "mma.sync.aligned.m16n8k8.row.col.f32.tf32.tf32.f32 "
                        "{%0,%1,%2,%3},{%4,%5,%6,%7},{%8,%9},{%0,%1,%2,%3};"
                        : "+f"(s[n][0]), "+f"(s[n][1]), "+f"(s[n][2]), "+f"(s[n][3])
                        : "r"(a0), "r"(a1), "r"(a2), "r"(a3), "r"(b0), "r"(b1));
                }
            }

            // ---- causal mask (only tiles straddling this warp's diagonal)
            if (kb + BLKK - 1 > myrow0) {
                int r0 = myrow0 + g, r1 = r0 + 8;
                #pragma unroll
                for (int n = 0; n < 8; n++) {
                    int c = kb + n * 8 + 2 * t;
                    if (c     > r0) s[n][0] = -1e30f;
                    if (c + 1 > r0) s[n][1] = -1e30f;
                    if (c     > r1) s[n][2] = -1e30f;
                    if (c + 1 > r1) s[n][3] = -1e30f;
                }
            }

            // ---- online softmax (rows g and g+8)
            float mx0 = -1e30f, mx1 = -1e30f;
            #pragma unroll
            for (int n = 0; n < 8; n++) {
                mx0 = fmaxf(mx0, fmaxf(s[n][0], s[n][1]));
                mx1 = fmaxf(mx1, fmaxf(s[n][2], s[n][3]));
            }
            mx0 = fmaxf(mx0, __shfl_xor_sync(0xffffffffu, mx0, 1));
            mx0 = fmaxf(mx0, __shfl_xor_sync(0xffffffffu, mx0, 2));
            mx1 = fmaxf(mx1, __shfl_xor_sync(0xffffffffu, mx1, 1));
            mx1 = fmaxf(mx1, __shfl_xor_sync(0xffffffffu, mx1, 2));
            float mn0 = fmaxf(m0, mx0), mn1 = fmaxf(m1, mx1);
            float al0 = __expf(m0 - mn0), al1 = __expf(m1 - mn1);
            float ls0 = 0.f, ls1 = 0.f;
            #pragma unroll
            for (int n = 0; n < 8; n++) {
                s[n][0] = __expf(s[n][0] - mn0);
                s[n][1] = __expf(s[n][1] - mn0);
                s[n][2] = __expf(s[n][2] - mn1);
                s[n][3] = __expf(s[n][3] - mn1);
                ls0 += s[n][0] + s[n][1];
                ls1 += s[n][2] + s[n][3];
            }
            ls0 += __shfl_xor_sync(0xffffffffu, ls0, 1);
            ls0 += __shfl_xor_sync(0xffffffffu, ls0, 2);
            ls1 += __shfl_xor_sync(0xffffffffu, ls1, 1);
            ls1 += __shfl_xor_sync(0xffffffffu, ls1, 2);
            l0 = l0 * al0 + ls0;  l1 = l1 * al1 + ls1;
            m0 = mn0;  m1 = mn1;
            #pragma unroll
            for (int nt = 0; nt < 16; nt++) {
                oa[nt][0] *= al0; oa[nt][1] *= al0;
                oa[nt][2] *= al1; oa[nt][3] *= al1;
            }

            // ---- O += P @ V  (P C-frag -> A-frag via quad shuffles)
            int src0 = (g << 2) | (t >> 1);
            int src1 = src0 + 2;
            bool odd = (t & 1);
            #pragma unroll
            for (int j = 0; j < 8; j++) {
                float x0 = __shfl_sync(0xffffffffu, s[j][0], src0);
                float y0 = __shfl_sync(0xffffffffu, s[j][1], src0);
                float x1 = __shfl_sync(0xffffffffu, s[j][0], src1);
                float y1 = __shfl_sync(0xffffffffu, s[j][1], src1);
                float x2 = __shfl_sync(0xffffffffu, s[j][2], src0);
                float y2 = __shfl_sync(0xffffffffu, s[j][3], src0);
                float x3 = __shfl_sync(0xffffffffu, s[j][2], src1);
                float y3 = __shfl_sync(0xffffffffu, s[j][3], src1);
                uint32_t a0 = __float_as_uint(odd ? y0 : x0);   // P[g   ][8j+t  ]
                uint32_t a1 = __float_as_uint(odd ? y2 : x2);   // P[g+8 ][8j+t  ]
                uint32_t a2 = __float_as_uint(odd ? y1 : x1);   // P[g   ][8j+t+4]
                uint32_t a3 = __float_as_uint(odd ? y3 : x3);   // P[g+8 ][8j+t+4]
                #pragma unroll
                for (int nt = 0; nt < 16; nt++) {
                    uint32_t b0 = __float_as_uint(Vb[(j * 8 + t)     * FSTR + nt * 8 + g]);
                    uint32_t b1 = __float_as_uint(Vb[(j * 8 + t + 4) * FSTR + nt * 8 + g]);
                    asm volatile(
                        "mma.sync.aligned.m16n8k8.row.col.f32.tf32.tf32.f32 "
                        "{%0,%1,%2,%3},{%4,%5,%6,%7},{%8,%9},{%0,%1,%2,%3};"
                        : "+f"(oa[nt][0]), "+f"(oa[nt][1]), "+f"(oa[nt][2]), "+f"(oa[nt][3])
                        : "r"(a0), "r"(a1), "r"(a2), "r"(a3), "r"(b0), "r"(b1));
                }
            }
        }
    }

    // ---- epilogue: normalize and store
    float inv0 = 1.0f / l0, inv1 = 1.0f / l1;
    int r0 = q0 + warp * 16 + g;
    size_t ob0 = (rowbase + r0) * HH + hoff;
    size_t ob1 = ob0 + (size_t)8 * HH;
    #pragma unroll
    for (int nt = 0; nt < 16; nt++) {
        int col = nt * 8 + 2 * t;
        float2 v0 = { oa[nt][0] * inv0, oa[nt][1] * inv0 };
        float2 v1 = { oa[nt][2] * inv1, oa[nt][3] * inv1 };
        *(float2*)(o + ob0 + col) = v0;
        *(float2*)(o + ob1 + col) = v1;
    }
}

// ---------------- launch ----------------------------------------------------
extern "C" void kernel_launch(void* const* d_in, const int* in_sizes, int n_in,
                              void* d_out, int out_size)
{
    const float* x        = (const float*)d_in[0];
    const float* ln_w     = (const float*)d_in[1];
    const float* ln_b     = (const float*)d_in[2];
    const float* c_attn_w = (const float*)d_in[3];
    const float* c_attn_b = (const float*)d_in[4];
    const float* c_proj_w = (const float*)d_in[5];
    const float* c_proj_b = (const float*)d_in[6];
    float* out = (float*)d_out;

    void *p_xn, *p_qkv, *p_o;
    cudaGetSymbolAddress(&p_xn,  g_xn);
    cudaGetSymbolAddress(&p_qkv, g_qkv);
    cudaGetSymbolAddress(&p_o,   g_o);
    float* xn  = (float*)p_xn;
    float* qkv = (float*)p_qkv;
    float* ov  = (float*)p_o;

    cudaFuncSetAttribute(gemm_tf32<true, false>,
                         cudaFuncAttributeMaxDynamicSharedMemorySize, GEMM_SMEM);
    cudaFuncSetAttribute(gemm_tf32<true, true>,
                         cudaFuncAttributeMaxDynamicSharedMemorySize, GEMM_SMEM);
    cudaFuncSetAttribute(flash_tc_kernel,
                         cudaFuncAttributeMaxDynamicSharedMemorySize, FLASH_SMEM);

    // 1. LayerNorm
    ln_kernel<<<MROWS, 256>>>(x, ln_w, ln_b, xn);

    // 2. QKV projection: [8192,2048] @ [2048,6144] + bias
    gemm_tf32<true, false><<<dim3(QKVN / 128, MROWS / 128), 256, GEMM_SMEM>>>(
        xn, c_attn_w, c_attn_b, nullptr, qkv, MROWS, QKVN, HH);

    // 3. causal flash attention (tensor cores)
    flash_tc_kernel<<<dim3(SS / BLKQ, BB * NHH), 256, FLASH_SMEM>>>(qkv, ov);

    // 4. output projection + bias + residual
    gemm_tf32<true, true><<<dim3(HH / 128, MROWS / 128), 256, GEMM_SMEM>>>(
        ov, c_proj_w, c_proj_b, x, out, MROWS, HH, HH);
}

// round 6
// speedup vs baseline: 1.9481x; 1.0560x over previous
#include <cuda_runtime.h>
#include <cstdint>

#define BB 4
#define SS 2048
#define HH 2048
#define NHH 16
#define HDD 128
#define MROWS (BB*SS)      /* 8192 */
#define QKVN (3*HH)        /* 6144 */

// ---------------- scratch (static device allocations are allowed) ----------
__device__ float g_xn [(size_t)MROWS * HH];
__device__ float g_qkv[(size_t)MROWS * QKVN];
__device__ float g_o  [(size_t)MROWS * HH];

__device__ __forceinline__ uint32_t smem_u32(const void* p) {
    uint32_t a;
    asm("{ .reg .u64 t; cvta.to.shared.u64 t, %1; cvt.u32.u64 %0, t; }"
        : "=r"(a) : "l"(p));
    return a;
}

// ---------------- LayerNorm ------------------------------------------------
__global__ void __launch_bounds__(256) ln_kernel(
    const float* __restrict__ x, const float* __restrict__ w,
    const float* __restrict__ b, float* __restrict__ out)
{
    int row = blockIdx.x;
    const float* xr = x + (size_t)row * HH;
    float v[8];
    float s = 0.f, s2 = 0.f;
    #pragma unroll
    for (int i = 0; i < 8; i++) {
        v[i] = xr[threadIdx.x + i * 256];
        s  += v[i];
        s2 += v[i] * v[i];
    }
    __shared__ float red0[8], red1[8];
    #pragma unroll
    for (int off = 16; off; off >>= 1) {
        s  += __shfl_xor_sync(0xffffffffu, s,  off);
        s2 += __shfl_xor_sync(0xffffffffu, s2, off);
    }
    int warp = threadIdx.x >> 5, lane = threadIdx.x & 31;
    if (lane == 0) { red0[warp] = s; red1[warp] = s2; }
    __syncthreads();
    if (warp == 0) {
        s  = red0[lane & 7];
        s2 = red1[lane & 7];
        #pragma unroll
        for (int off = 4; off; off >>= 1) {
            s  += __shfl_xor_sync(0xffffffffu, s,  off);
            s2 += __shfl_xor_sync(0xffffffffu, s2, off);
        }
        if (lane == 0) { red0[0] = s; red1[0] = s2; }
    }
    __syncthreads();
    float mu  = red0[0] * (1.f / HH);
    float var = red1[0] * (1.f / HH) - mu * mu;
    float rs  = rsqrtf(var + 1e-5f);
    float* orow = out + (size_t)row * HH;
    #pragma unroll
    for (int i = 0; i < 8; i++) {
        int c = threadIdx.x + i * 256;
        orow[c] = (v[i] - mu) * rs * w[c] + b[c];
    }
}

// ---------------- TF32 GEMM, cp.async 3-stage, 64x64 warp tiles ------------
// Block tile: 256(M) x 128(N), K-stage = 32. 8 warps in 4x2 grid, 64x64 each.
// cp.async.cg feeds raw fp32 to HMMA.TF32 (mantissa truncation ~2^-11 rel).

#define GSTG 3
#define GASTR 36
#define GBSTR 136
#define GASZ (256 * GASTR)
#define GBSZ (32 * GBSTR)
#define GEMM_SMEM (GSTG * (GASZ + GBSZ) * (int)sizeof(float))   /* 162816 B */

template<bool BIAS, bool RES>
__global__ void __launch_bounds__(256, 1) gemm_tc(
    const float* __restrict__ A, const float* __restrict__ Bm,
    const float* __restrict__ bias, const float* __restrict__ res,
    float* __restrict__ C, int M, int N, int K)
{
    extern __shared__ float sm[];
    float* As = sm;
    float* Bs = sm + GSTG * GASZ;

    int tid  = threadIdx.x;
    int warp = tid >> 5, lane = tid & 31;
    int g = lane >> 2, t = lane & 3;
    int wm = (warp >> 1) * 64;
    int wn = (warp & 1) * 64;
    int bm = blockIdx.y * 256;
    int bn = blockIdx.x * 128;

    float acc[4][8][4];
    #pragma unroll
    for (int mi = 0; mi < 4; mi++)
        #pragma unroll
        for (int ni = 0; ni < 8; ni++)
            #pragma unroll
            for (int c = 0; c < 4; c++) acc[mi][ni][c] = 0.f;

    const int KT = K >> 5;

    auto issue = [&](int kt) {
        int kk = kt * 32;
        float* Ab = As + (kt % GSTG) * GASZ;
        float* Bb = Bs + (kt % GSTG) * GBSZ;
        #pragma unroll
        for (int p = 0; p < 8; p++) {
            int idx = tid + p * 256;              // 2048 float4s of A
            int r = idx >> 3, c4 = (idx & 7) * 4;
            uint32_t d = smem_u32(Ab + r * GASTR + c4);
            const float* s = A + (size_t)(bm + r) * K + kk + c4;
            asm volatile("cp.async.cg.shared.global [%0], [%1], 16;" :: "r"(d), "l"(s) : "memory");
        }
        #pragma unroll
        for (int p = 0; p < 4; p++) {
            int idx = tid + p * 256;              // 1024 float4s of B
            int r = idx >> 5, c4 = (idx & 31) * 4;
            uint32_t d = smem_u32(Bb + r * GBSTR + c4);
            const float* s = Bm + (size_t)(kk + r) * N + bn + c4;
            asm volatile("cp.async.cg.shared.global [%0], [%1], 16;" :: "r"(d), "l"(s) : "memory");
        }
        asm volatile("cp.async.commit_group;" ::: "memory");
    };

    issue(0);
    issue(1);

    for (int kt = 0; kt < KT; kt++) {
        asm volatile("cp.async.wait_group 1;" ::: "memory");
        __syncthreads();                          // stage kt ready; buf (kt+2)%3 free
        if (kt + 2 < KT) issue(kt + 2);

        float* Ab = As + (kt % GSTG) * GASZ;
        float* Bb = Bs + (kt % GSTG) * GBSZ;

        #pragma unroll
        for (int ks = 0; ks < 4; ks++) {
            int k0 = ks * 8;
            uint32_t af[4][4], bf[8][2];
            #pragma unroll
            for (int mi = 0; mi < 4; mi++) {
                int r0 = (wm + mi * 16 + g) * GASTR;
                int r1 = r0 + 8 * GASTR;
                af[mi][0] = __float_as_uint(Ab[r0 + k0 + t]);
                af[mi][1] = __float_as_uint(Ab[r1 + k0 + t]);
                af[mi][2] = __float_as_uint(Ab[r0 + k0 + t + 4]);
                af[mi][3] = __float_as_uint(Ab[r1 + k0 + t + 4]);
            }
            #pragma unroll
            for (int ni = 0; ni < 8; ni++) {
                int cn = wn + ni * 8 + g;
                bf[ni][0] = __float_as_uint(Bb[(k0 + t)     * GBSTR + cn]);
                bf[ni][1] = __float_as_uint(Bb[(k0 + t + 4) * GBSTR + cn]);
            }
            #pragma unroll
            for (int mi = 0; mi < 4; mi++)
                #pragma unroll
                for (int ni = 0; ni < 8; ni++)
                    asm volatile(
                        "mma.sync.aligned.m16n8k8.row.col.f32.tf32.tf32.f32 "
                        "{%0,%1,%2,%3},{%4,%5,%6,%7},{%8,%9},{%0,%1,%2,%3};"
                        : "+f"(acc[mi][ni][0]), "+f"(acc[mi][ni][1]),
                          "+f"(acc[mi][ni][2]), "+f"(acc[mi][ni][3])
                        : "r"(af[mi][0]), "r"(af[mi][1]), "r"(af[mi][2]), "r"(af[mi][3]),
                          "r"(bf[ni][0]), "r"(bf[ni][1]));
        }
    }

    // ---- epilogue
    #pragma unroll
    for (int mi = 0; mi < 4; mi++) {
        int r0 = bm + wm + mi * 16 + g;
        #pragma unroll
        for (int ni = 0; ni < 8; ni++) {
            int c0 = bn + wn + ni * 8 + 2 * t;
            #pragma unroll
            for (int half = 0; half < 2; half++) {
                int row = r0 + half * 8;
                float2 v;
                v.x = acc[mi][ni][half * 2 + 0];
                v.y = acc[mi][ni][half * 2 + 1];
                if (BIAS) { v.x += bias[c0]; v.y += bias[c0 + 1]; }
                if (RES) {
                    float2 rr = *(const float2*)(res + (size_t)row * N + c0);
                    v.x += rr.x; v.y += rr.y;
                }
                *(float2*)(C + (size_t)row * N + c0) = v;
            }
        }
    }
}

// ---------------- tensor-core (tf32) flash attention ------------------------
#define BLKQ 128
#define BLKK 64
#define FSTR 136
#define KVSZ (BLKK * FSTR)
#define FLASH_SMEM ((BLKQ * FSTR + 4 * KVSZ) * (int)sizeof(float))  /* 208896 B */

__global__ void __launch_bounds__(256) flash_tc_kernel(
    const float* __restrict__ qkv, float* __restrict__ o)
{
    extern __shared__ float sm[];
    float* Qs = sm;                         // [128][FSTR]
    float* KV = sm + BLKQ * FSTR;           // 2 x (K[64][FSTR], V[64][FSTR])

    int tid  = threadIdx.x;
    int warp = tid >> 5, lane = tid & 31;
    int g = lane >> 2, t = lane & 3;
    int qt = 15 - (int)blockIdx.x;          // heavy tiles first
    int bh = blockIdx.y;
    int b = bh >> 4, h = bh & 15;
    int q0 = qt * BLKQ;
    size_t rowbase = (size_t)b * SS;
    size_t hoff = (size_t)h * 128;
    const float scale = 0.08838834764831845f;   // 1/sqrt(128)

    // ---- load Q (scaled) into smem
    #pragma unroll
    for (int i = 0; i < 16; i++) {
        int idx = tid + i * 256;            // 4096 float4s
        int r = idx >> 5, c4 = (idx & 31) * 4;
        float4 v = *(const float4*)(qkv + (rowbase + q0 + r) * QKVN + hoff + c4);
        float* d = Qs + r * FSTR + c4;
        d[0] = v.x * scale; d[1] = v.y * scale;
        d[2] = v.z * scale; d[3] = v.w * scale;
    }

    auto issue_tile = [&](int kt) {
        int kb = kt * BLKK;
        float* Kb = KV + (kt & 1) * 2 * KVSZ;
        float* Vb = Kb + KVSZ;
        #pragma unroll
        for (int i = 0; i < 8; i++) {
            int idx = tid + i * 256;        // 2048 float4s per operand
            int r = idx >> 5, c4 = (idx & 31) * 4;
            const float* gk = qkv + (rowbase + kb + r) * QKVN + hoff + 2048 + c4;
            const float* gv = gk + 2048;
            uint32_t sk = smem_u32(Kb + r * FSTR + c4);
            uint32_t sv = smem_u32(Vb + r * FSTR + c4);
            asm volatile("cp.async.cg.shared.global [%0], [%1], 16;" :: "r"(sk), "l"(gk) : "memory");
            asm volatile("cp.async.cg.shared.global [%0], [%1], 16;" :: "r"(sv), "l"(gv) : "memory");
        }
        asm volatile("cp.async.commit_group;" ::: "memory");
    };

    float m0 = -1e30f, m1 = -1e30f, l0 = 0.f, l1 = 0.f;
    float oa[16][4];
    #pragma unroll
    for (int nt = 0; nt < 16; nt++)
        #pragma unroll
        for (int c = 0; c < 4; c++) oa[nt][c] = 0.f;

    const int NKT = (q0 + BLKQ) / BLKK;     // 2*qt + 2
    const int myrow0 = q0 + warp * 16;      // first q row of this warp
    const int arow0 = (warp * 16 + g) * FSTR;
    const int arow1 = arow0 + 8 * FSTR;

    issue_tile(0);

    for (int kt = 0; kt < NKT; kt++) {
        int kb = kt * BLKK;
        asm volatile("cp.async.wait_group 0;" ::: "memory");
        __syncthreads();                     // tile kt visible; prev tile's bufs free
        if (kt + 1 < NKT) issue_tile(kt + 1);

        bool active = (kb <= myrow0 + 15);   // warp-uniform
        float* Kb = KV + (kt & 1) * 2 * KVSZ;
        float* Vb = Kb + KVSZ;

        if (active) {
            // ---- S = Q @ K^T  (128 mmas/warp)
            float s[8][4];
            #pragma unroll
            for (int n = 0; n < 8; n++)
                #pragma unroll
                for (int c = 0; c < 4; c++) s[n][c] = 0.f;

            #pragma unroll
            for (int k = 0; k < 16; k++) {
                int k0 = k * 8;
                uint32_t a0 = __float_as_uint(Qs[arow0 + k0 + t]);
                uint32_t a1 = __float_as_uint(Qs[arow1 + k0 + t]);
                uint32_t a2 = __float_as_uint(Qs[arow0 + k0 + t + 4]);
                uint32_t a3 = __float_as_uint(Qs[arow1 + k0 + t + 4]);
                #pragma unroll
                for (int n = 0; n < 8; n++) {
                    uint32_t b0 = __float_as_uint(Kb[(n * 8 + g) * FSTR + k0 + t]);
                    uint32_t b1 = __float_as_uint(Kb[(n * 8 + g) * FSTR + k0 + t + 4]);
                    asm volatile(
                        "mma.sync.aligned.m16n8k8.row.col.f32.tf32.tf32.f32 "
                        "{%0,%1,%2,%3},{%4,%5,%6,%7},{%8,%9},{%0,%1,%2,%3};"
                        : "+f"(s[n][0]), "+f"(s[n][1]), "+f"(s[n][2]), "+f"(s[n][3])
                        : "r"(a0), "r"(a1), "r"(a2), "r"(a3), "r"(b0), "r"(b1));
                }
            }

            // ---- causal mask (only tiles straddling this warp's diagonal)
            if (kb + BLKK - 1 > myrow0) {
                int r0 = myrow0 + g, r1 = r0 + 8;
                #pragma unroll
                for (int n = 0; n < 8; n++) {
                    int c = kb + n * 8 + 2 * t;
                    if (c     > r0) s[n][0] = -1e30f;
                    if (c + 1 > r0) s[n][1] = -1e30f;
                    if (c     > r1) s[n][2] = -1e30f;
                    if (c + 1 > r1) s[n][3] = -1e30f;
                }
            }

            // ---- online softmax (rows g and g+8)
            float mx0 = -1e30f, mx1 = -1e30f;
            #pragma unroll
            for (int n = 0; n < 8; n++) {
                mx0 = fmaxf(mx0, fmaxf(s[n][0], s[n][1]));
                mx1 = fmaxf(mx1, fmaxf(s[n][2], s[n][3]));
            }
            mx0 = fmaxf(mx0, __shfl_xor_sync(0xffffffffu, mx0, 1));
            mx0 = fmaxf(mx0, __shfl_xor_sync(0xffffffffu, mx0, 2));
            mx1 = fmaxf(mx1, __shfl_xor_sync(0xffffffffu, mx1, 1));
            mx1 = fmaxf(mx1, __shfl_xor_sync(0xffffffffu, mx1, 2));
            float mn0 = fmaxf(m0, mx0), mn1 = fmaxf(m1, mx1);
            float al0 = __expf(m0 - mn0), al1 = __expf(m1 - mn1);
            float ls0 = 0.f, ls1 = 0.f;
            #pragma unroll
            for (int n = 0; n < 8; n++) {
                s[n][0] = __expf(s[n][0] - mn0);
                s[n][1] = __expf(s[n][1] - mn0);
                s[n][2] = __expf(s[n][2] - mn1);
                s[n][3] = __expf(s[n][3] - mn1);
                ls0 += s[n][0] + s[n][1];
                ls1 += s[n][2] + s[n][3];
            }
            ls0 += __shfl_xor_sync(0xffffffffu, ls0, 1);
            ls0 += __shfl_xor_sync(0xffffffffu, ls0, 2);
            ls1 += __shfl_xor_sync(0xffffffffu, ls1, 1);
            ls1 += __shfl_xor_sync(0xffffffffu, ls1, 2);
            l0 = l0 * al0 + ls0;  l1 = l1 * al1 + ls1;
            m0 = mn0;  m1 = mn1;
            #pragma unroll
            for (int nt = 0; nt < 16; nt++) {
                oa[nt][0] *= al0; oa[nt][1] *= al0;
                oa[nt][2] *= al1; oa[nt][3] *= al1;
            }

            // ---- O += P @ V  (P C-frag -> A-frag via quad shuffles)
            int src0 = (g << 2) | (t >> 1);
            int src1 = src0 + 2;
            bool odd = (t & 1);
            #pragma unroll
            for (int j = 0; j < 8; j++) {
                float x0 = __shfl_sync(0xffffffffu, s[j][0], src0);
                float y0 = __shfl_sync(0xffffffffu, s[j][1], src0);
                float x1 = __shfl_sync(0xffffffffu, s[j][0], src1);
                float y1 = __shfl_sync(0xffffffffu, s[j][1], src1);
                float x2 = __shfl_sync(0xffffffffu, s[j][2], src0);
                float y2 = __shfl_sync(0xffffffffu, s[j][3], src0);
                float x3 = __shfl_sync(0xffffffffu, s[j][2], src1);
                float y3 = __shfl_sync(0xffffffffu, s[j][3], src1);
                uint32_t a0 = __float_as_uint(odd ? y0 : x0);   // P[g   ][8j+t  ]
                uint32_t a1 = __float_as_uint(odd ? y2 : x2);   // P[g+8 ][8j+t  ]
                uint32_t a2 = __float_as_uint(odd ? y1 : x1);   // P[g   ][8j+t+4]
                uint32_t a3 = __float_as_uint(odd ? y3 : x3);   // P[g+8 ][8j+t+4]
                #pragma unroll
                for (int nt = 0; nt < 16; nt++) {
                    uint32_t b0 = __float_as_uint(Vb[(j * 8 + t)     * FSTR + nt * 8 + g]);
                    uint32_t b1 = __float_as_uint(Vb[(j * 8 + t + 4) * FSTR + nt * 8 + g]);
                    asm volatile(
                        "mma.sync.aligned.m16n8k8.row.col.f32.tf32.tf32.f32 "
                        "{%0,%1,%2,%3},{%4,%5,%6,%7},{%8,%9},{%0,%1,%2,%3};"
                        : "+f"(oa[nt][0]), "+f"(oa[nt][1]), "+f"(oa[nt][2]), "+f"(oa[nt][3])
                        : "r"(a0), "r"(a1), "r"(a2), "r"(a3), "r"(b0), "r"(b1));
                }
            }
        }
    }

    // ---- epilogue: normalize and store
    float inv0 = 1.0f / l0, inv1 = 1.0f / l1;
    int r0 = q0 + warp * 16 + g;
    size_t ob0 = (rowbase + r0) * HH + hoff;
    size_t ob1 = ob0 + (size_t)8 * HH;
    #pragma unroll
    for (int nt = 0; nt < 16; nt++) {
        int col = nt * 8 + 2 * t;
        float2 v0 = { oa[nt][0] * inv0, oa[nt][1] * inv0 };
        float2 v1 = { oa[nt][2] * inv1, oa[nt][3] * inv1 };
        *(float2*)(o + ob0 + col) = v0;
        *(float2*)(o + ob1 + col) = v1;
    }
}

// ---------------- launch ----------------------------------------------------
extern "C" void kernel_launch(void* const* d_in, const int* in_sizes, int n_in,
                              void* d_out, int out_size)
{
    const float* x        = (const float*)d_in[0];
    const float* ln_w     = (const float*)d_in[1];
    const float* ln_b     = (const float*)d_in[2];
    const float* c_attn_w = (const float*)d_in[3];
    const float* c_attn_b = (const float*)d_in[4];
    const float* c_proj_w = (const float*)d_in[5];
    const float* c_proj_b = (const float*)d_in[6];
    float* out = (float*)d_out;

    void *p_xn, *p_qkv, *p_o;
    cudaGetSymbolAddress(&p_xn,  g_xn);
    cudaGetSymbolAddress(&p_qkv, g_qkv);
    cudaGetSymbolAddress(&p_o,   g_o);
    float* xn  = (float*)p_xn;
    float* qkv = (float*)p_qkv;
    float* ov  = (float*)p_o;

    cudaFuncSetAttribute(gemm_tc<true, false>,
                         cudaFuncAttributeMaxDynamicSharedMemorySize, GEMM_SMEM);
    cudaFuncSetAttribute(gemm_tc<true, true>,
                         cudaFuncAttributeMaxDynamicSharedMemorySize, GEMM_SMEM);
    cudaFuncSetAttribute(flash_tc_kernel,
                         cudaFuncAttributeMaxDynamicSharedMemorySize, FLASH_SMEM);

    // 1. LayerNorm
    ln_kernel<<<MROWS, 256>>>(x, ln_w, ln_b, xn);

    // 2. QKV projection: [8192,2048] @ [2048,6144] + bias
    gemm_tc<true, false><<<dim3(QKVN / 128, MROWS / 256), 256, GEMM_SMEM>>>(
        xn, c_attn_w, c_attn_b, nullptr, qkv, MROWS, QKVN, HH);

    // 3. causal flash attention (tensor cores)
    flash_tc_kernel<<<dim3(SS / BLKQ, BB * NHH), 256, FLASH_SMEM>>>(qkv, ov);

    // 4. output projection + bias + residual
    gemm_tc<true, true><<<dim3(HH / 128, MROWS / 256), 256, GEMM_SMEM>>>(
        ov, c_proj_w, c_proj_b, x, out, MROWS, HH, HH);
}